// round 14
// baseline (speedup 1.0000x reference)
#include <cuda_runtime.h>
#include <stdint.h>
#include <math.h>

// Problem constants (fixed by setup_inputs)
#define BATCH 2
#define SEQ   2048
#define DIM   1024
#define HEADS 16
#define DHEAD 64
#define MROWS (BATCH*SEQ)   // 4096
#define N3    (3*DIM)       // 3072
#define HALFW 64

// Scratch. "p" = K-packed layout: within each 8-group along K,
// order is [0,4,1,5,2,6,3,7]  (packpos(k) = 2*(k&3) + (k>>2)).
__device__ float g_xnp [(size_t)MROWS * DIM];
__device__ float g_qkv [(size_t)MROWS * N3];
__device__ float g_attp[(size_t)MROWS * DIM];
__device__ float g_wqkvp[(size_t)N3 * DIM];
__device__ float g_woutp[(size_t)DIM * DIM];

// ---------------------------------------------------------------------------
// helpers
// ---------------------------------------------------------------------------
__device__ __forceinline__ unsigned f2tf32(float x) {
    unsigned r;
    asm("cvt.rna.tf32.f32 %0, %1;" : "=r"(r) : "f"(x));
    return r;
}

__device__ __forceinline__ void mma_tf32(float c[4], const unsigned a[4],
                                         const unsigned b[2]) {
    asm volatile(
        "mma.sync.aligned.m16n8k8.row.col.f32.tf32.tf32.f32 "
        "{%0,%1,%2,%3}, {%4,%5,%6,%7}, {%8,%9}, {%0,%1,%2,%3};"
        : "+f"(c[0]), "+f"(c[1]), "+f"(c[2]), "+f"(c[3])
        : "r"(a[0]), "r"(a[1]), "r"(a[2]), "r"(a[3]), "r"(b[0]), "r"(b[1]));
}

__device__ __forceinline__ void cp16(unsigned saddr, const void* g) {
    asm volatile("cp.async.cg.shared.global [%0], [%1], 16;\n"
                 :: "r"(saddr), "l"(g));
}

#define MBAR_INIT(addr, cnt) \
    asm volatile("mbarrier.init.shared.b64 [%0], %1;" :: "r"(addr), "r"(cnt) : "memory")

#define MBAR_ARRIVE(addr) \
    asm volatile("mbarrier.arrive.shared.b64 _, [%0];" :: "r"(addr) : "memory")

#define CPASYNC_MBAR_ARRIVE(addr) \
    asm volatile("cp.async.mbarrier.arrive.noinc.shared.b64 [%0];" :: "r"(addr) : "memory")

#define MBAR_WAIT_PARITY(mbar_smem_addr, phase_parity) do { \
    uint32_t _mbar = (uint32_t)(mbar_smem_addr); \
    uint32_t _parity = (uint32_t)(phase_parity); \
    uint32_t _done; \
    asm volatile( \
        "{\n\t.reg .pred p;\n\t" \
        "mbarrier.try_wait.parity.acquire.cta.shared::cta.b64 p, [%1], %2;\n\t" \
        "selp.b32 %0, 1, 0, p;\n\t}" \
        : "=r"(_done) : "r"(_mbar), "r"(_parity) : "memory"); \
    if (!_done) { \
        asm volatile( \
            "{\n\t.reg .pred P1;\n\t" \
            "WAIT_LOOP_%=:\n\t" \
            "mbarrier.try_wait.parity.acquire.cta.shared::cta.b64 P1, [%0], %1, 0x989680;\n\t" \
            "@P1 bra.uni WAIT_DONE_%=;\n\t" \
            "bra.uni WAIT_LOOP_%=;\n\t" \
            "WAIT_DONE_%=:\n\t}" \
            :: "r"(_mbar), "r"(_parity) : "memory"); \
    } \
} while (0)

// ---------------------------------------------------------------------------
// pack kernel: permute K within 8-groups (thread = one group of 8)
// ---------------------------------------------------------------------------
__global__ void pack_kernel(const float* __restrict__ src,
                            float* __restrict__ dst) {
    size_t i = (size_t)blockIdx.x * 256 + threadIdx.x;
    const float4* s = (const float4*)src;
    float4 v0 = s[i * 2];
    float4 v1 = s[i * 2 + 1];
    float4* d = (float4*)dst;
    d[i * 2]     = make_float4(v0.x, v1.x, v0.y, v1.y);   // [0,4,1,5]
    d[i * 2 + 1] = make_float4(v0.z, v1.z, v0.w, v1.w);   // [2,6,3,7]
}

// ---------------------------------------------------------------------------
// RMSNorm: one block per row, 128 threads, 8 floats/thread, packed output
// ---------------------------------------------------------------------------
__global__ void rmsnorm_kernel(const float* __restrict__ x,
                               const float* __restrict__ w) {
    int row = blockIdx.x;
    int t = threadIdx.x;
    const float4* xr = (const float4*)(x + (size_t)row * DIM);
    float4 v0 = xr[t * 2];
    float4 v1 = xr[t * 2 + 1];
    float ss = v0.x*v0.x + v0.y*v0.y + v0.z*v0.z + v0.w*v0.w
             + v1.x*v1.x + v1.y*v1.y + v1.z*v1.z + v1.w*v1.w;
    __shared__ float red[4];
    #pragma unroll
    for (int off = 16; off > 0; off >>= 1)
        ss += __shfl_xor_sync(0xffffffff, ss, off);
    if ((t & 31) == 0) red[t >> 5] = ss;
    __syncthreads();
    float tot = red[0] + red[1] + red[2] + red[3];
    float inv = rsqrtf(tot * (1.0f / DIM) + 1e-6f);
    const float4* wv = (const float4*)w;
    float4 w0 = wv[t * 2], w1 = wv[t * 2 + 1];
    float r0 = v0.x * inv * w0.x, r1 = v0.y * inv * w0.y;
    float r2 = v0.z * inv * w0.z, r3 = v0.w * inv * w0.w;
    float r4 = v1.x * inv * w1.x, r5 = v1.y * inv * w1.y;
    float r6 = v1.z * inv * w1.z, r7 = v1.w * inv * w1.w;
    float4* o = (float4*)(g_xnp + (size_t)row * DIM);
    o[t * 2]     = make_float4(r0, r4, r1, r5);
    o[t * 2 + 1] = make_float4(r2, r6, r3, r7);
}

// ---------------------------------------------------------------------------
// Warp-specialized TF32 GEMM on PACKED operands, 2 CTAs/SM.  (unchanged R13)
// ---------------------------------------------------------------------------
#define GBM 128
#define GBN 128
#define GBK 16
#define KST 24
#define NST 4
#define A_STG (GBM * KST)
#define B_STG (GBN * KST)
#define STG_FLOATS (A_STG + B_STG)
#define GEMM_SMEM (NST * STG_FLOATS * sizeof(float) + 128)

__global__ __launch_bounds__(320, 2)
void gemm_tf32_kernel(const float* __restrict__ A,
                      const float* __restrict__ B,
                      const float* __restrict__ skip,
                      float* __restrict__ C,
                      int M, int N, int K) {
    extern __shared__ float smg[];
    uint32_t smbase = (uint32_t)__cvta_generic_to_shared(smg);
    uint32_t mbar   = smbase + NST * STG_FLOATS * 4;

    int t   = threadIdx.x;
    int m0  = blockIdx.y * GBM;
    int n0  = blockIdx.x * GBN;
    int nk  = K / GBK;
    int nko = nk / NST;

    if (t == 0) {
        #pragma unroll
        for (int s = 0; s < NST; s++) {
            MBAR_INIT(mbar + s * 8, 64);
            MBAR_INIT(mbar + 32 + s * 8, 8);
        }
    }
    __syncthreads();

    if (t >= 256) {
        int p = t - 256;
        const float* Asrc[8];
        const float* Bsrc[8];
        uint32_t Adst[8], Bdst[8];
        #pragma unroll
        for (int i = 0; i < 8; i++) {
            int id = p + 64 * i, r = id >> 2, q = id & 3;
            Asrc[i] = A + (size_t)(m0 + r) * K + q * 4;
            Adst[i] = smbase + (r * KST + q * 4) * 4;
            Bsrc[i] = B + (size_t)(n0 + r) * K + q * 4;
            Bdst[i] = smbase + A_STG * 4 + (r * KST + q * 4) * 4;
        }
        int koff = 0;
        for (int ko = 0; ko < nko; ko++) {
            int ph = 1 ^ (ko & 1);
            #pragma unroll
            for (int s = 0; s < NST; s++) {
                MBAR_WAIT_PARITY(mbar + 32 + s * 8, ph);
                const uint32_t soff = s * STG_FLOATS * 4;
                #pragma unroll
                for (int i = 0; i < 8; i++)
                    cp16(Adst[i] + soff, Asrc[i] + koff + s * GBK);
                #pragma unroll
                for (int i = 0; i < 8; i++)
                    cp16(Bdst[i] + soff, Bsrc[i] + koff + s * GBK);
                CPASYNC_MBAR_ARRIVE(mbar + s * 8);
            }
            koff += NST * GBK;
        }
        return;
    }

    int lane = t & 31;
    int wid  = t >> 5;
    int wm   = (wid >> 1) * 32;
    int wn   = (wid & 1) * 64;
    int gid  = lane >> 2;
    int tig  = lane & 3;

    const int aoff = (wm + gid) * KST + tig * 2;
    const int boff = A_STG + (wn + gid) * KST + tig * 2;

    float acc[2][8][4] = {};

    for (int ko = 0; ko < nko; ko++) {
        int ph = ko & 1;
        #pragma unroll
        for (int s = 0; s < NST; s++) {
            MBAR_WAIT_PARITY(mbar + s * 8, ph);
            const float* sbase = smg + s * STG_FLOATS;
            #pragma unroll
            for (int kk = 0; kk < 2; kk++) {
                const float* pa = sbase + aoff + kk * 8;
                const float* pb = sbase + boff + kk * 8;
                unsigned af[2][4];
                #pragma unroll
                for (int mi = 0; mi < 2; mi++) {
                    float2 x0 = *(const float2*)(pa + (mi * 16) * KST);
                    float2 x1 = *(const float2*)(pa + (mi * 16 + 8) * KST);
                    af[mi][0] = __float_as_uint(x0.x);
                    af[mi][1] = __float_as_uint(x1.x);
                    af[mi][2] = __float_as_uint(x0.y);
                    af[mi][3] = __float_as_uint(x1.y);
                }
                #pragma unroll
                for (int ni = 0; ni < 8; ni++) {
                    float2 bb = *(const float2*)(pb + (ni * 8) * KST);
                    unsigned bf[2] = { __float_as_uint(bb.x), __float_as_uint(bb.y) };
                    mma_tf32(acc[0][ni], af[0], bf);
                    mma_tf32(acc[1][ni], af[1], bf);
                }
            }
            __syncwarp();
            if (lane == 0) MBAR_ARRIVE(mbar + 32 + s * 8);
        }
    }

    #pragma unroll
    for (int mi = 0; mi < 2; mi++) {
        #pragma unroll
        for (int ni = 0; ni < 8; ni++) {
            int r0  = m0 + wm + mi * 16 + gid;
            int col = n0 + wn + ni * 8 + tig * 2;
            float2 v0 = make_float2(acc[mi][ni][0], acc[mi][ni][1]);
            float2 v1 = make_float2(acc[mi][ni][2], acc[mi][ni][3]);
            size_t o0 = (size_t)r0 * N + col;
            size_t o1 = (size_t)(r0 + 8) * N + col;
            if (skip) {
                float2 s0 = *(const float2*)(skip + o0);
                float2 s1 = *(const float2*)(skip + o1);
                v0.x += s0.x; v0.y += s0.y;
                v1.x += s1.x; v1.y += s1.y;
            }
            *(float2*)(C + o0) = v0;
            *(float2*)(C + o1) = v1;
        }
    }
}

// ---------------------------------------------------------------------------
// Banded attention, TQ=64 (tf32 mma.sync). One block per (b,h,64-query tile).
// Key span 192. Output written K-PACKED into g_attp.
// ---------------------------------------------------------------------------
#define TQ   64
#define SPAN 192
#define QST  68
#define KSTR 68
#define VTST 197
#define SST  197
#define ATTN_SMEM ((TQ * QST + SPAN * KSTR + DHEAD * VTST + TQ * SST) * sizeof(float))

__global__ __launch_bounds__(256) void attn_kernel() {
    extern __shared__ float sm[];
    float* Qs = sm;                       // 64 x 68
    float* Ks = Qs + TQ * QST;            // 192 x 68
    float* Vt = Ks + SPAN * KSTR;         // 64 x 197 (transposed V)
    float* Ss = Vt + DHEAD * VTST;        // 64 x 197

    int t    = threadIdx.x;
    int lane = t & 31;
    int w    = t >> 5;
    int gid  = lane >> 2;
    int tig  = lane & 3;
    int bh = blockIdx.y;
    int b  = bh >> 4, h = bh & 15;
    int q0 = blockIdx.x * TQ;
    int kstart = q0 - HALFW;
    size_t base = (size_t)(b * SEQ) * N3;

    // load Q (64 rows x 16 float4)
    for (int idx = t; idx < TQ * 16; idx += 256) {
        int i  = idx >> 4;
        int d4 = idx & 15;
        float4 v = *(const float4*)&g_qkv[base + (size_t)(q0 + i) * N3 + h * DHEAD + d4 * 4];
        float* dst = &Qs[i * QST + d4 * 4];
        dst[0] = __uint_as_float(f2tf32(v.x));
        dst[1] = __uint_as_float(f2tf32(v.y));
        dst[2] = __uint_as_float(f2tf32(v.z));
        dst[3] = __uint_as_float(f2tf32(v.w));
    }
    // load K rows + V transposed (zero-fill out-of-range)
    for (int idx = t; idx < SPAN * 16; idx += 256) {
        int jj = idx >> 4;
        int d4 = idx & 15;
        int j  = kstart + jj;
        float4 kv = make_float4(0, 0, 0, 0), vv = kv;
        if (j >= 0 && j < SEQ) {
            kv = *(const float4*)&g_qkv[base + (size_t)j * N3 + DIM     + h * DHEAD + d4 * 4];
            vv = *(const float4*)&g_qkv[base + (size_t)j * N3 + 2 * DIM + h * DHEAD + d4 * 4];
        }
        float* kd = &Ks[jj * KSTR + d4 * 4];
        kd[0] = __uint_as_float(f2tf32(kv.x));
        kd[1] = __uint_as_float(f2tf32(kv.y));
        kd[2] = __uint_as_float(f2tf32(kv.z));
        kd[3] = __uint_as_float(f2tf32(kv.w));
        int d0 = d4 * 4;
        Vt[(d0 + 0) * VTST + jj] = __uint_as_float(f2tf32(vv.x));
        Vt[(d0 + 1) * VTST + jj] = __uint_as_float(f2tf32(vv.y));
        Vt[(d0 + 2) * VTST + jj] = __uint_as_float(f2tf32(vv.z));
        Vt[(d0 + 3) * VTST + jj] = __uint_as_float(f2tf32(vv.w));
    }
    __syncthreads();

    // S = Q K^T / 8, band-masked. Warp w: m-tile (w&3), n-tiles (w>>2)*12..+11
    {
        int mt = w & 3;
        int ng = w >> 2;
        unsigned afr[8][4];
        #pragma unroll
        for (int kk = 0; kk < 8; kk++) {
            int mr = mt * 16 + gid;
            int kb = kk * 8;
            afr[kk][0] = __float_as_uint(Qs[mr * QST + kb + tig]);
            afr[kk][1] = __float_as_uint(Qs[(mr + 8) * QST + kb + tig]);
            afr[kk][2] = __float_as_uint(Qs[mr * QST + kb + tig + 4]);
            afr[kk][3] = __float_as_uint(Qs[(mr + 8) * QST + kb + tig + 4]);
        }
        #pragma unroll
        for (int l = 0; l < 12; l++) {
            int nt = ng * 12 + l;
            int nr = nt * 8 + gid;
            float acc[4] = {0.f, 0.f, 0.f, 0.f};
            #pragma unroll
            for (int kk = 0; kk < 8; kk++) {
                unsigned bfr[2];
                bfr[0] = __float_as_uint(Ks[nr * KSTR + kk * 8 + tig]);
                bfr[1] = __float_as_uint(Ks[nr * KSTR + kk * 8 + tig + 4]);
                mma_tf32(acc, afr[kk], bfr);
            }
            int i0  = mt * 16 + gid;
            int col = nt * 8 + tig * 2;
            #pragma unroll
            for (int rr = 0; rr < 2; rr++) {
                int i = i0 + rr * 8;
                int qi = q0 + i;
                #pragma unroll
                for (int c = 0; c < 2; c++) {
                    int jj = col + c;
                    int j  = kstart + jj;
                    int di = qi - j; if (di < 0) di = -di;
                    bool valid = (j >= 0) && (j < SEQ) && (di <= HALFW);
                    Ss[i * SST + jj] = valid ? acc[rr * 2 + c] * 0.125f : -1e30f;
                }
            }
        }
    }
    __syncthreads();

    // softmax: warp w handles rows 8w..8w+7, 6 cols per lane (192 = 32*6)
    #pragma unroll
    for (int r = 0; r < 8; r++) {
        int i = w * 8 + r;
        float vals[6];
        float vmax = -1e30f;
        #pragma unroll
        for (int c = 0; c < 6; c++) {
            vals[c] = Ss[i * SST + lane + 32 * c];
            vmax = fmaxf(vmax, vals[c]);
        }
        #pragma unroll
        for (int off = 16; off > 0; off >>= 1)
            vmax = fmaxf(vmax, __shfl_xor_sync(0xffffffff, vmax, off));
        float sum = 0.0f;
        #pragma unroll
        for (int c = 0; c < 6; c++) {
            vals[c] = __expf(vals[c] - vmax);
            sum += vals[c];
        }
        #pragma unroll
        for (int off = 16; off > 0; off >>= 1)
            sum += __shfl_xor_sync(0xffffffff, sum, off);
        float inv = 1.0f / sum;
        #pragma unroll
        for (int c = 0; c < 6; c++)
            Ss[i * SST + lane + 32 * c] = __uint_as_float(f2tf32(vals[c] * inv));
    }
    __syncthreads();

    // O = P V. Warp w: m-tile (w&3), n-tiles (w>>2)*4..+3, K = 24 k8-steps
    {
        int mt = w & 3;
        int ng = w >> 2;
        float acc[4][4] = {};
        int mrb = mt * 16 + gid;
        #pragma unroll
        for (int kk = 0; kk < 24; kk++) {
            int kb = kk * 8;
            unsigned afr[4];
            afr[0] = __float_as_uint(Ss[mrb * SST + kb + tig]);
            afr[1] = __float_as_uint(Ss[(mrb + 8) * SST + kb + tig]);
            afr[2] = __float_as_uint(Ss[mrb * SST + kb + tig + 4]);
            afr[3] = __float_as_uint(Ss[(mrb + 8) * SST + kb + tig + 4]);
            #pragma unroll
            for (int l = 0; l < 4; l++) {
                int nr = (ng * 4 + l) * 8 + gid;
                unsigned bf[2];
                bf[0] = __float_as_uint(Vt[nr * VTST + kb + tig]);
                bf[1] = __float_as_uint(Vt[nr * VTST + kb + tig + 4]);
                mma_tf32(acc[l], afr, bf);
            }
        }
        // packed store: packpos(c) = 2*(c&3) + (c>>2) within each 8-group
        size_t ob = (size_t)(b * SEQ + q0) * DIM + h * DHEAD;
        int r0 = mt * 16 + gid;
        #pragma unroll
        for (int l = 0; l < 4; l++) {
            int colg = (ng * 4 + l) * 8;
            #pragma unroll
            for (int rr = 0; rr < 2; rr++) {
                int row = r0 + rr * 8;
                float* orow = &g_attp[ob + (size_t)row * DIM];
                #pragma unroll
                for (int c = 0; c < 2; c++) {
                    int k  = tig * 2 + c;
                    int pk = 2 * (k & 3) + (k >> 2);
                    orow[colg + pk] = acc[l][rr * 2 + c];
                }
            }
        }
    }
}

// ---------------------------------------------------------------------------
// launch
// ---------------------------------------------------------------------------
extern "C" void kernel_launch(void* const* d_in, const int* in_sizes, int n_in,
                              void* d_out, int out_size) {
    const float* x      = (const float*)d_in[0];
    const float* w_norm = (const float*)d_in[1];
    const float* w_qkv  = (const float*)d_in[2];
    const float* w_out  = (const float*)d_in[3];
    float* out = (float*)d_out;

    float *p_xnp, *p_qkv, *p_attp, *p_wqp, *p_wop;
    cudaGetSymbolAddress((void**)&p_xnp,  g_xnp);
    cudaGetSymbolAddress((void**)&p_qkv,  g_qkv);
    cudaGetSymbolAddress((void**)&p_attp, g_attp);
    cudaGetSymbolAddress((void**)&p_wqp,  g_wqkvp);
    cudaGetSymbolAddress((void**)&p_wop,  g_woutp);

    cudaFuncSetAttribute(gemm_tf32_kernel, cudaFuncAttributeMaxDynamicSharedMemorySize,
                         (int)GEMM_SMEM);
    cudaFuncSetAttribute(attn_kernel, cudaFuncAttributeMaxDynamicSharedMemorySize,
                         (int)ATTN_SMEM);

    // 0. pack weights (K-interleave within 8-groups)
    pack_kernel<<<(N3 * DIM / 8) / 256, 256>>>(w_qkv, p_wqp);
    pack_kernel<<<(DIM * DIM / 8) / 256, 256>>>(w_out, p_wop);

    // 1. RMSNorm -> packed xn
    rmsnorm_kernel<<<MROWS, 128>>>(x, w_norm);

    // 2. QKV projection (warp-specialized, packed operands, 2 CTA/SM)
    {
        dim3 grid(N3 / GBN, MROWS / GBM);
        gemm_tf32_kernel<<<grid, 320, GEMM_SMEM>>>(p_xnp, p_wqp, nullptr, p_qkv,
                                                   MROWS, N3, DIM);
    }

    // 3. Banded attention (TQ=64) -> packed att
    {
        dim3 grid(SEQ / TQ, BATCH * HEADS);
        attn_kernel<<<grid, 256, ATTN_SMEM>>>();
    }

    // 4. Output projection + residual (warp-specialized, packed operands)
    {
        dim3 grid(DIM / GBN, MROWS / GBM);
        gemm_tf32_kernel<<<grid, 320, GEMM_SMEM>>>(p_attp, p_wop, x, out,
                                                   MROWS, DIM, DIM);
    }
}

// round 15
// speedup vs baseline: 1.0701x; 1.0701x over previous
#include <cuda_runtime.h>
#include <stdint.h>
#include <math.h>

// Problem constants (fixed by setup_inputs)
#define BATCH 2
#define SEQ   2048
#define DIM   1024
#define HEADS 16
#define DHEAD 64
#define MROWS (BATCH*SEQ)   // 4096
#define N3    (3*DIM)       // 3072
#define HALFW 64

// Scratch. "p" = K-packed layout: within each 8-group along K,
// order is [0,4,1,5,2,6,3,7]  (packpos(k) = 2*(k&3) + (k>>2)).
__device__ float g_xnp [(size_t)MROWS * DIM];
__device__ float g_qkv [(size_t)MROWS * N3];
__device__ float g_attp[(size_t)MROWS * DIM];
__device__ float g_wqkvp[(size_t)N3 * DIM];
__device__ float g_woutp[(size_t)DIM * DIM];

// ---------------------------------------------------------------------------
// helpers
// ---------------------------------------------------------------------------
__device__ __forceinline__ unsigned f2tf32(float x) {
    unsigned r;
    asm("cvt.rna.tf32.f32 %0, %1;" : "=r"(r) : "f"(x));
    return r;
}

__device__ __forceinline__ void mma_tf32(float c[4], const unsigned a[4],
                                         const unsigned b[2]) {
    asm volatile(
        "mma.sync.aligned.m16n8k8.row.col.f32.tf32.tf32.f32 "
        "{%0,%1,%2,%3}, {%4,%5,%6,%7}, {%8,%9}, {%0,%1,%2,%3};"
        : "+f"(c[0]), "+f"(c[1]), "+f"(c[2]), "+f"(c[3])
        : "r"(a[0]), "r"(a[1]), "r"(a[2]), "r"(a[3]), "r"(b[0]), "r"(b[1]));
}

__device__ __forceinline__ void cp16(unsigned saddr, const void* g) {
    asm volatile("cp.async.cg.shared.global [%0], [%1], 16;\n"
                 :: "r"(saddr), "l"(g));
}

#define MBAR_INIT(addr, cnt) \
    asm volatile("mbarrier.init.shared.b64 [%0], %1;" :: "r"(addr), "r"(cnt) : "memory")

#define MBAR_ARRIVE(addr) \
    asm volatile("mbarrier.arrive.shared.b64 _, [%0];" :: "r"(addr) : "memory")

#define CPASYNC_MBAR_ARRIVE(addr) \
    asm volatile("cp.async.mbarrier.arrive.noinc.shared.b64 [%0];" :: "r"(addr) : "memory")

#define MBAR_WAIT_PARITY(mbar_smem_addr, phase_parity) do { \
    uint32_t _mbar = (uint32_t)(mbar_smem_addr); \
    uint32_t _parity = (uint32_t)(phase_parity); \
    uint32_t _done; \
    asm volatile( \
        "{\n\t.reg .pred p;\n\t" \
        "mbarrier.try_wait.parity.acquire.cta.shared::cta.b64 p, [%1], %2;\n\t" \
        "selp.b32 %0, 1, 0, p;\n\t}" \
        : "=r"(_done) : "r"(_mbar), "r"(_parity) : "memory"); \
    if (!_done) { \
        asm volatile( \
            "{\n\t.reg .pred P1;\n\t" \
            "WAIT_LOOP_%=:\n\t" \
            "mbarrier.try_wait.parity.acquire.cta.shared::cta.b64 P1, [%0], %1, 0x989680;\n\t" \
            "@P1 bra.uni WAIT_DONE_%=;\n\t" \
            "bra.uni WAIT_LOOP_%=;\n\t" \
            "WAIT_DONE_%=:\n\t}" \
            :: "r"(_mbar), "r"(_parity) : "memory"); \
    } \
} while (0)

// ---------------------------------------------------------------------------
// pack kernel: permute K within 8-groups (thread = one group of 8)
// ---------------------------------------------------------------------------
__global__ void pack_kernel(const float* __restrict__ src,
                            float* __restrict__ dst) {
    size_t i = (size_t)blockIdx.x * 256 + threadIdx.x;
    const float4* s = (const float4*)src;
    float4 v0 = s[i * 2];
    float4 v1 = s[i * 2 + 1];
    float4* d = (float4*)dst;
    d[i * 2]     = make_float4(v0.x, v1.x, v0.y, v1.y);   // [0,4,1,5]
    d[i * 2 + 1] = make_float4(v0.z, v1.z, v0.w, v1.w);   // [2,6,3,7]
}

// ---------------------------------------------------------------------------
// RMSNorm: one block per row, 128 threads, 8 floats/thread, packed output
// ---------------------------------------------------------------------------
__global__ void rmsnorm_kernel(const float* __restrict__ x,
                               const float* __restrict__ w) {
    int row = blockIdx.x;
    int t = threadIdx.x;
    const float4* xr = (const float4*)(x + (size_t)row * DIM);
    float4 v0 = xr[t * 2];
    float4 v1 = xr[t * 2 + 1];
    float ss = v0.x*v0.x + v0.y*v0.y + v0.z*v0.z + v0.w*v0.w
             + v1.x*v1.x + v1.y*v1.y + v1.z*v1.z + v1.w*v1.w;
    __shared__ float red[4];
    #pragma unroll
    for (int off = 16; off > 0; off >>= 1)
        ss += __shfl_xor_sync(0xffffffff, ss, off);
    if ((t & 31) == 0) red[t >> 5] = ss;
    __syncthreads();
    float tot = red[0] + red[1] + red[2] + red[3];
    float inv = rsqrtf(tot * (1.0f / DIM) + 1e-6f);
    const float4* wv = (const float4*)w;
    float4 w0 = wv[t * 2], w1 = wv[t * 2 + 1];
    float r0 = v0.x * inv * w0.x, r1 = v0.y * inv * w0.y;
    float r2 = v0.z * inv * w0.z, r3 = v0.w * inv * w0.w;
    float r4 = v1.x * inv * w1.x, r5 = v1.y * inv * w1.y;
    float r6 = v1.z * inv * w1.z, r7 = v1.w * inv * w1.w;
    float4* o = (float4*)(g_xnp + (size_t)row * DIM);
    o[t * 2]     = make_float4(r0, r4, r1, r5);
    o[t * 2 + 1] = make_float4(r2, r6, r3, r7);
}

// ---------------------------------------------------------------------------
// Warp-specialized TF32 GEMM on PACKED operands, 2 CTAs/SM.  (unchanged R13)
// ---------------------------------------------------------------------------
#define GBM 128
#define GBN 128
#define GBK 16
#define KST 24
#define NST 4
#define A_STG (GBM * KST)
#define B_STG (GBN * KST)
#define STG_FLOATS (A_STG + B_STG)
#define GEMM_SMEM (NST * STG_FLOATS * sizeof(float) + 128)

__global__ __launch_bounds__(320, 2)
void gemm_tf32_kernel(const float* __restrict__ A,
                      const float* __restrict__ B,
                      const float* __restrict__ skip,
                      float* __restrict__ C,
                      int M, int N, int K) {
    extern __shared__ float smg[];
    uint32_t smbase = (uint32_t)__cvta_generic_to_shared(smg);
    uint32_t mbar   = smbase + NST * STG_FLOATS * 4;

    int t   = threadIdx.x;
    int m0  = blockIdx.y * GBM;
    int n0  = blockIdx.x * GBN;
    int nk  = K / GBK;
    int nko = nk / NST;

    if (t == 0) {
        #pragma unroll
        for (int s = 0; s < NST; s++) {
            MBAR_INIT(mbar + s * 8, 64);
            MBAR_INIT(mbar + 32 + s * 8, 8);
        }
    }
    __syncthreads();

    if (t >= 256) {
        int p = t - 256;
        const float* Asrc[8];
        const float* Bsrc[8];
        uint32_t Adst[8], Bdst[8];
        #pragma unroll
        for (int i = 0; i < 8; i++) {
            int id = p + 64 * i, r = id >> 2, q = id & 3;
            Asrc[i] = A + (size_t)(m0 + r) * K + q * 4;
            Adst[i] = smbase + (r * KST + q * 4) * 4;
            Bsrc[i] = B + (size_t)(n0 + r) * K + q * 4;
            Bdst[i] = smbase + A_STG * 4 + (r * KST + q * 4) * 4;
        }
        int koff = 0;
        for (int ko = 0; ko < nko; ko++) {
            int ph = 1 ^ (ko & 1);
            #pragma unroll
            for (int s = 0; s < NST; s++) {
                MBAR_WAIT_PARITY(mbar + 32 + s * 8, ph);
                const uint32_t soff = s * STG_FLOATS * 4;
                #pragma unroll
                for (int i = 0; i < 8; i++)
                    cp16(Adst[i] + soff, Asrc[i] + koff + s * GBK);
                #pragma unroll
                for (int i = 0; i < 8; i++)
                    cp16(Bdst[i] + soff, Bsrc[i] + koff + s * GBK);
                CPASYNC_MBAR_ARRIVE(mbar + s * 8);
            }
            koff += NST * GBK;
        }
        return;
    }

    int lane = t & 31;
    int wid  = t >> 5;
    int wm   = (wid >> 1) * 32;
    int wn   = (wid & 1) * 64;
    int gid  = lane >> 2;
    int tig  = lane & 3;

    const int aoff = (wm + gid) * KST + tig * 2;
    const int boff = A_STG + (wn + gid) * KST + tig * 2;

    float acc[2][8][4] = {};

    for (int ko = 0; ko < nko; ko++) {
        int ph = ko & 1;
        #pragma unroll
        for (int s = 0; s < NST; s++) {
            MBAR_WAIT_PARITY(mbar + s * 8, ph);
            const float* sbase = smg + s * STG_FLOATS;
            #pragma unroll
            for (int kk = 0; kk < 2; kk++) {
                const float* pa = sbase + aoff + kk * 8;
                const float* pb = sbase + boff + kk * 8;
                unsigned af[2][4];
                #pragma unroll
                for (int mi = 0; mi < 2; mi++) {
                    float2 x0 = *(const float2*)(pa + (mi * 16) * KST);
                    float2 x1 = *(const float2*)(pa + (mi * 16 + 8) * KST);
                    af[mi][0] = __float_as_uint(x0.x);
                    af[mi][1] = __float_as_uint(x1.x);
                    af[mi][2] = __float_as_uint(x0.y);
                    af[mi][3] = __float_as_uint(x1.y);
                }
                #pragma unroll
                for (int ni = 0; ni < 8; ni++) {
                    float2 bb = *(const float2*)(pb + (ni * 8) * KST);
                    unsigned bf[2] = { __float_as_uint(bb.x), __float_as_uint(bb.y) };
                    mma_tf32(acc[0][ni], af[0], bf);
                    mma_tf32(acc[1][ni], af[1], bf);
                }
            }
            __syncwarp();
            if (lane == 0) MBAR_ARRIVE(mbar + 32 + s * 8);
        }
    }

    #pragma unroll
    for (int mi = 0; mi < 2; mi++) {
        #pragma unroll
        for (int ni = 0; ni < 8; ni++) {
            int r0  = m0 + wm + mi * 16 + gid;
            int col = n0 + wn + ni * 8 + tig * 2;
            float2 v0 = make_float2(acc[mi][ni][0], acc[mi][ni][1]);
            float2 v1 = make_float2(acc[mi][ni][2], acc[mi][ni][3]);
            size_t o0 = (size_t)r0 * N + col;
            size_t o1 = (size_t)(r0 + 8) * N + col;
            if (skip) {
                float2 s0 = *(const float2*)(skip + o0);
                float2 s1 = *(const float2*)(skip + o1);
                v0.x += s0.x; v0.y += s0.y;
                v1.x += s1.x; v1.y += s1.y;
            }
            *(float2*)(C + o0) = v0;
            *(float2*)(C + o1) = v1;
        }
    }
}

// ---------------------------------------------------------------------------
// Banded attention TQ=32 (tf32 mma.sync), 2 CTAs/SM via Qs/Ss smem aliasing.
// Layout: [Ss (aliases Qs) 32x165][Ks 160x68][Vt 64x165]  = 106.9 KB
// ---------------------------------------------------------------------------
#define TQ   32
#define SPAN 160
#define QST  68
#define KSTR 68
#define VTST 165
#define SST  165
#define ATTN_SMEM ((TQ * SST + SPAN * KSTR + DHEAD * VTST) * sizeof(float))

__global__ __launch_bounds__(256, 2) void attn_kernel() {
    extern __shared__ float sm[];
    float* Ss = sm;                       // TQ * SST (aliases Qs)
    float* Qs = sm;                       // TQ * QST (dead after frag load)
    float* Ks = sm + TQ * SST;            // SPAN * KSTR
    float* Vt = Ks + SPAN * KSTR;         // DHEAD * VTST

    int t    = threadIdx.x;
    int lane = t & 31;
    int w    = t >> 5;
    int gid  = lane >> 2;
    int tig  = lane & 3;
    int bh = blockIdx.y;
    int b  = bh >> 4, h = bh & 15;
    int q0 = blockIdx.x * TQ;
    int kstart = q0 - HALFW;
    size_t base = (size_t)(b * SEQ) * N3;

    // Phase 1: load Q (to aliased region), K, Vt
    for (int idx = t; idx < TQ * 16; idx += 256) {
        int i  = idx >> 4;
        int d4 = idx & 15;
        float4 v = *(const float4*)&g_qkv[base + (size_t)(q0 + i) * N3 + h * DHEAD + d4 * 4];
        float* dst = &Qs[i * QST + d4 * 4];
        dst[0] = __uint_as_float(f2tf32(v.x));
        dst[1] = __uint_as_float(f2tf32(v.y));
        dst[2] = __uint_as_float(f2tf32(v.z));
        dst[3] = __uint_as_float(f2tf32(v.w));
    }
    for (int idx = t; idx < SPAN * 16; idx += 256) {
        int jj = idx >> 4;
        int d4 = idx & 15;
        int j  = kstart + jj;
        float4 kv = make_float4(0, 0, 0, 0), vv = kv;
        if (j >= 0 && j < SEQ) {
            kv = *(const float4*)&g_qkv[base + (size_t)j * N3 + DIM     + h * DHEAD + d4 * 4];
            vv = *(const float4*)&g_qkv[base + (size_t)j * N3 + 2 * DIM + h * DHEAD + d4 * 4];
        }
        float* kd = &Ks[jj * KSTR + d4 * 4];
        kd[0] = __uint_as_float(f2tf32(kv.x));
        kd[1] = __uint_as_float(f2tf32(kv.y));
        kd[2] = __uint_as_float(f2tf32(kv.z));
        kd[3] = __uint_as_float(f2tf32(kv.w));
        int d0 = d4 * 4;
        Vt[(d0 + 0) * VTST + jj] = __uint_as_float(f2tf32(vv.x));
        Vt[(d0 + 1) * VTST + jj] = __uint_as_float(f2tf32(vv.y));
        Vt[(d0 + 2) * VTST + jj] = __uint_as_float(f2tf32(vv.z));
        Vt[(d0 + 3) * VTST + jj] = __uint_as_float(f2tf32(vv.w));
    }
    __syncthreads();

    // Phase 2: every warp loads its Q fragments into registers; then barrier
    // so the Qs region can be overwritten by Ss.
    int mt = w & 1;
    int ng = w >> 1;
    unsigned afr[8][4];
    {
        int mr = mt * 16 + gid;
        #pragma unroll
        for (int kk = 0; kk < 8; kk++) {
            int kb = kk * 8;
            afr[kk][0] = __float_as_uint(Qs[mr * QST + kb + tig]);
            afr[kk][1] = __float_as_uint(Qs[(mr + 8) * QST + kb + tig]);
            afr[kk][2] = __float_as_uint(Qs[mr * QST + kb + tig + 4]);
            afr[kk][3] = __float_as_uint(Qs[(mr + 8) * QST + kb + tig + 4]);
        }
    }
    __syncthreads();   // all Q reads done before Ss overwrites the region

    // Phase 3: S = Q K^T / 8, band-masked. Warp w: m-tile mt, n-tiles ng*5..+4
    {
        #pragma unroll
        for (int l = 0; l < 5; l++) {
            int nt = ng * 5 + l;
            int nr = nt * 8 + gid;
            float acc[4] = {0.f, 0.f, 0.f, 0.f};
            #pragma unroll
            for (int kk = 0; kk < 8; kk++) {
                unsigned bfr[2];
                bfr[0] = __float_as_uint(Ks[nr * KSTR + kk * 8 + tig]);
                bfr[1] = __float_as_uint(Ks[nr * KSTR + kk * 8 + tig + 4]);
                mma_tf32(acc, afr[kk], bfr);
            }
            int i0  = mt * 16 + gid;
            int col = nt * 8 + tig * 2;
            #pragma unroll
            for (int rr = 0; rr < 2; rr++) {
                int i = i0 + rr * 8;
                int qi = q0 + i;
                #pragma unroll
                for (int c = 0; c < 2; c++) {
                    int jj = col + c;
                    int j  = kstart + jj;
                    int di = qi - j; if (di < 0) di = -di;
                    bool valid = (j >= 0) && (j < SEQ) && (di <= HALFW);
                    Ss[i * SST + jj] = valid ? acc[rr * 2 + c] * 0.125f : -1e30f;
                }
            }
        }
    }
    __syncthreads();

    // softmax: warp w handles rows 4w..4w+3, 5 cols per lane
    #pragma unroll
    for (int r = 0; r < 4; r++) {
        int i = w * 4 + r;
        float vals[5];
        float vmax = -1e30f;
        #pragma unroll
        for (int c = 0; c < 5; c++) {
            vals[c] = Ss[i * SST + lane + 32 * c];
            vmax = fmaxf(vmax, vals[c]);
        }
        #pragma unroll
        for (int off = 16; off > 0; off >>= 1)
            vmax = fmaxf(vmax, __shfl_xor_sync(0xffffffff, vmax, off));
        float sum = 0.0f;
        #pragma unroll
        for (int c = 0; c < 5; c++) {
            vals[c] = __expf(vals[c] - vmax);
            sum += vals[c];
        }
        #pragma unroll
        for (int off = 16; off > 0; off >>= 1)
            sum += __shfl_xor_sync(0xffffffff, sum, off);
        float inv = 1.0f / sum;
        #pragma unroll
        for (int c = 0; c < 5; c++)
            Ss[i * SST + lane + 32 * c] = __uint_as_float(f2tf32(vals[c] * inv));
    }
    __syncthreads();

    // O = P V. Warp w: m-tile mt, output n-tiles ng and ng+4
    {
        float acc0[4] = {0.f, 0.f, 0.f, 0.f};
        float acc1[4] = {0.f, 0.f, 0.f, 0.f};
        int n0r = ng * 8 + gid;
        int n1r = (ng + 4) * 8 + gid;
        #pragma unroll
        for (int kk = 0; kk < 20; kk++) {
            int kb = kk * 8;
            int mr = mt * 16 + gid;
            unsigned pfr[4];
            pfr[0] = __float_as_uint(Ss[mr * SST + kb + tig]);
            pfr[1] = __float_as_uint(Ss[(mr + 8) * SST + kb + tig]);
            pfr[2] = __float_as_uint(Ss[mr * SST + kb + tig + 4]);
            pfr[3] = __float_as_uint(Ss[(mr + 8) * SST + kb + tig + 4]);
            unsigned b0[2], b1[2];
            b0[0] = __float_as_uint(Vt[n0r * VTST + kb + tig]);
            b0[1] = __float_as_uint(Vt[n0r * VTST + kb + tig + 4]);
            b1[0] = __float_as_uint(Vt[n1r * VTST + kb + tig]);
            b1[1] = __float_as_uint(Vt[n1r * VTST + kb + tig + 4]);
            mma_tf32(acc0, pfr, b0);
            mma_tf32(acc1, pfr, b1);
        }
        // packed store: packpos(c) = 2*(c&3) + (c>>2) within each 8-group
        size_t ob = (size_t)(b * SEQ + q0) * DIM + h * DHEAD;
        int r0 = mt * 16 + gid;
        int c1base = (ng + 4) * 8;
        float vals4[2][4] = {{acc0[0], acc0[1], acc1[0], acc1[1]},
                             {acc0[2], acc0[3], acc1[2], acc1[3]}};
        #pragma unroll
        for (int rr = 0; rr < 2; rr++) {
            int row = r0 + rr * 8;
            float* orow = &g_attp[ob + (size_t)row * DIM];
            #pragma unroll
            for (int c = 0; c < 4; c++) {
                int colg = (c < 2) ? ng * 8 : c1base;
                int k    = (c & 1) ? tig * 2 + 1 : tig * 2;
                int pk   = 2 * (k & 3) + (k >> 2);
                orow[colg + pk] = vals4[rr][c];
            }
        }
    }
}

// ---------------------------------------------------------------------------
// launch
// ---------------------------------------------------------------------------
extern "C" void kernel_launch(void* const* d_in, const int* in_sizes, int n_in,
                              void* d_out, int out_size) {
    const float* x      = (const float*)d_in[0];
    const float* w_norm = (const float*)d_in[1];
    const float* w_qkv  = (const float*)d_in[2];
    const float* w_out  = (const float*)d_in[3];
    float* out = (float*)d_out;

    float *p_xnp, *p_qkv, *p_attp, *p_wqp, *p_wop;
    cudaGetSymbolAddress((void**)&p_xnp,  g_xnp);
    cudaGetSymbolAddress((void**)&p_qkv,  g_qkv);
    cudaGetSymbolAddress((void**)&p_attp, g_attp);
    cudaGetSymbolAddress((void**)&p_wqp,  g_wqkvp);
    cudaGetSymbolAddress((void**)&p_wop,  g_woutp);

    cudaFuncSetAttribute(gemm_tf32_kernel, cudaFuncAttributeMaxDynamicSharedMemorySize,
                         (int)GEMM_SMEM);
    cudaFuncSetAttribute(attn_kernel, cudaFuncAttributeMaxDynamicSharedMemorySize,
                         (int)ATTN_SMEM);

    // 0. pack weights (K-interleave within 8-groups)
    pack_kernel<<<(N3 * DIM / 8) / 256, 256>>>(w_qkv, p_wqp);
    pack_kernel<<<(DIM * DIM / 8) / 256, 256>>>(w_out, p_wop);

    // 1. RMSNorm -> packed xn
    rmsnorm_kernel<<<MROWS, 128>>>(x, w_norm);

    // 2. QKV projection (warp-specialized, packed operands, 2 CTA/SM)
    {
        dim3 grid(N3 / GBN, MROWS / GBM);
        gemm_tf32_kernel<<<grid, 320, GEMM_SMEM>>>(p_xnp, p_wqp, nullptr, p_qkv,
                                                   MROWS, N3, DIM);
    }

    // 3. Banded attention (TQ=32, 2 CTA/SM) -> packed att
    {
        dim3 grid(SEQ / TQ, BATCH * HEADS);
        attn_kernel<<<grid, 256, ATTN_SMEM>>>();
    }

    // 4. Output projection + residual (warp-specialized, packed operands)
    {
        dim3 grid(DIM / GBN, MROWS / GBM);
        gemm_tf32_kernel<<<grid, 320, GEMM_SMEM>>>(p_attp, p_wop, x, out,
                                                   MROWS, DIM, DIM);
    }
}

// round 17
// speedup vs baseline: 1.4100x; 1.3176x over previous
#include <cuda_runtime.h>
#include <cuda_fp16.h>
#include <stdint.h>
#include <math.h>

// Problem constants (fixed by setup_inputs)
#define BATCH 2
#define SEQ   2048
#define DIM   1024
#define HEADS 16
#define DHEAD 64
#define MROWS (BATCH*SEQ)   // 4096
#define N3    (3*DIM)       // 3072
#define HALFW 64

// Scratch. GEMM operands are fp16, K-packed in 16-groups with order
// [0,1,8,9, 2,3,10,11, 4,5,12,13, 6,7,14,15]  (thread tig's LDS.64 at
// offset 4*tig yields k = {2t,2t+1,2t+8,2t+9} = full m16n8k16 fragment).
__device__ __half g_xnp [(size_t)MROWS * DIM];
__device__ float  g_qkv [(size_t)MROWS * N3];
__device__ __half g_attp[(size_t)MROWS * DIM];
__device__ __half g_wqkvp[(size_t)N3 * DIM];
__device__ __half g_woutp[(size_t)DIM * DIM];

// ---------------------------------------------------------------------------
// helpers
// ---------------------------------------------------------------------------
__device__ __forceinline__ unsigned f2tf32(float x) {
    unsigned r;
    asm("cvt.rna.tf32.f32 %0, %1;" : "=r"(r) : "f"(x));
    return r;
}

__device__ __forceinline__ void mma_tf32(float c[4], const unsigned a[4],
                                         const unsigned b[2]) {
    asm volatile(
        "mma.sync.aligned.m16n8k8.row.col.f32.tf32.tf32.f32 "
        "{%0,%1,%2,%3}, {%4,%5,%6,%7}, {%8,%9}, {%0,%1,%2,%3};"
        : "+f"(c[0]), "+f"(c[1]), "+f"(c[2]), "+f"(c[3])
        : "r"(a[0]), "r"(a[1]), "r"(a[2]), "r"(a[3]), "r"(b[0]), "r"(b[1]));
}

__device__ __forceinline__ void mma_f16(float c[4], unsigned a0, unsigned a1,
                                        unsigned a2, unsigned a3,
                                        unsigned b0, unsigned b1) {
    asm volatile(
        "mma.sync.aligned.m16n8k16.row.col.f32.f16.f16.f32 "
        "{%0,%1,%2,%3}, {%4,%5,%6,%7}, {%8,%9}, {%0,%1,%2,%3};"
        : "+f"(c[0]), "+f"(c[1]), "+f"(c[2]), "+f"(c[3])
        : "r"(a0), "r"(a1), "r"(a2), "r"(a3), "r"(b0), "r"(b1));
}

__device__ __forceinline__ void cp16(unsigned saddr, const void* g) {
    asm volatile("cp.async.cg.shared.global [%0], [%1], 16;\n"
                 :: "r"(saddr), "l"(g));
}

#define MBAR_INIT(addr, cnt) \
    asm volatile("mbarrier.init.shared.b64 [%0], %1;" :: "r"(addr), "r"(cnt) : "memory")

#define MBAR_ARRIVE(addr) \
    asm volatile("mbarrier.arrive.shared.b64 _, [%0];" :: "r"(addr) : "memory")

#define CPASYNC_MBAR_ARRIVE(addr) \
    asm volatile("cp.async.mbarrier.arrive.noinc.shared.b64 [%0];" :: "r"(addr) : "memory")

#define MBAR_WAIT_PARITY(mbar_smem_addr, phase_parity) do { \
    uint32_t _mbar = (uint32_t)(mbar_smem_addr); \
    uint32_t _parity = (uint32_t)(phase_parity); \
    uint32_t _done; \
    asm volatile( \
        "{\n\t.reg .pred p;\n\t" \
        "mbarrier.try_wait.parity.acquire.cta.shared::cta.b64 p, [%1], %2;\n\t" \
        "selp.b32 %0, 1, 0, p;\n\t}" \
        : "=r"(_done) : "r"(_mbar), "r"(_parity) : "memory"); \
    if (!_done) { \
        asm volatile( \
            "{\n\t.reg .pred P1;\n\t" \
            "WAIT_LOOP_%=:\n\t" \
            "mbarrier.try_wait.parity.acquire.cta.shared::cta.b64 P1, [%0], %1, 0x989680;\n\t" \
            "@P1 bra.uni WAIT_DONE_%=;\n\t" \
            "bra.uni WAIT_LOOP_%=;\n\t" \
            "WAIT_DONE_%=:\n\t}" \
            :: "r"(_mbar), "r"(_parity) : "memory"); \
    } \
} while (0)

// ---------------------------------------------------------------------------
// pack kernel: fp32 -> fp16, K-interleaved in 16-groups (thread = one group)
// ---------------------------------------------------------------------------
__global__ void pack_kernel(const float* __restrict__ src,
                            __half* __restrict__ dst) {
    size_t i = (size_t)blockIdx.x * 256 + threadIdx.x;
    const float4* s = (const float4*)src + i * 4;
    float4 v0 = s[0];   // k 0-3
    float4 v1 = s[1];   // k 4-7
    float4 v2 = s[2];   // k 8-11
    float4 v3 = s[3];   // k 12-15
    __half2* d = (__half2*)(dst + i * 16);
    d[0] = __floats2half2_rn(v0.x, v0.y);   // k0,1
    d[1] = __floats2half2_rn(v2.x, v2.y);   // k8,9
    d[2] = __floats2half2_rn(v0.z, v0.w);   // k2,3
    d[3] = __floats2half2_rn(v2.z, v2.w);   // k10,11
    d[4] = __floats2half2_rn(v1.x, v1.y);   // k4,5
    d[5] = __floats2half2_rn(v3.x, v3.y);   // k12,13
    d[6] = __floats2half2_rn(v1.z, v1.w);   // k6,7
    d[7] = __floats2half2_rn(v3.z, v3.w);   // k14,15
}

// ---------------------------------------------------------------------------
// RMSNorm: one block per row, 64 threads, 16 floats/thread, packed f16 output
// ---------------------------------------------------------------------------
__global__ void rmsnorm_kernel(const float* __restrict__ x,
                               const float* __restrict__ w) {
    int row = blockIdx.x;
    int t = threadIdx.x;   // 0..63
    const float4* xr = (const float4*)(x + (size_t)row * DIM) + t * 4;
    float4 v0 = xr[0], v1 = xr[1], v2 = xr[2], v3 = xr[3];
    float ss = v0.x*v0.x + v0.y*v0.y + v0.z*v0.z + v0.w*v0.w
             + v1.x*v1.x + v1.y*v1.y + v1.z*v1.z + v1.w*v1.w
             + v2.x*v2.x + v2.y*v2.y + v2.z*v2.z + v2.w*v2.w
             + v3.x*v3.x + v3.y*v3.y + v3.z*v3.z + v3.w*v3.w;
    __shared__ float red[2];
    #pragma unroll
    for (int off = 16; off > 0; off >>= 1)
        ss += __shfl_xor_sync(0xffffffff, ss, off);
    if ((t & 31) == 0) red[t >> 5] = ss;
    __syncthreads();
    float inv = rsqrtf((red[0] + red[1]) * (1.0f / DIM) + 1e-6f);
    const float4* wv = (const float4*)w + t * 4;
    float4 w0 = wv[0], w1 = wv[1], w2 = wv[2], w3 = wv[3];
    float4 r0 = make_float4(v0.x*inv*w0.x, v0.y*inv*w0.y, v0.z*inv*w0.z, v0.w*inv*w0.w);
    float4 r1 = make_float4(v1.x*inv*w1.x, v1.y*inv*w1.y, v1.z*inv*w1.z, v1.w*inv*w1.w);
    float4 r2 = make_float4(v2.x*inv*w2.x, v2.y*inv*w2.y, v2.z*inv*w2.z, v2.w*inv*w2.w);
    float4 r3 = make_float4(v3.x*inv*w3.x, v3.y*inv*w3.y, v3.z*inv*w3.z, v3.w*inv*w3.w);
    __half2* d = (__half2*)(g_xnp + (size_t)row * DIM + t * 16);
    d[0] = __floats2half2_rn(r0.x, r0.y);
    d[1] = __floats2half2_rn(r2.x, r2.y);
    d[2] = __floats2half2_rn(r0.z, r0.w);
    d[3] = __floats2half2_rn(r2.z, r2.w);
    d[4] = __floats2half2_rn(r1.x, r1.y);
    d[5] = __floats2half2_rn(r3.x, r3.y);
    d[6] = __floats2half2_rn(r1.z, r1.w);
    d[7] = __floats2half2_rn(r3.z, r3.w);
}

// ---------------------------------------------------------------------------
// Warp-specialized FP16 GEMM on PACKED operands, 2 CTAs/SM.
// C[M,N] = A[M,K] @ B[N,K]^T (+skip fp32). CTA tile 128x128, k16 chunks.
// 8 consumer warps (32x64) + 2 producer warps; 8-stage mbarrier ring.
// Row stride 16 halfs (32B, zero pad) -> conflict-free LDS.64 frag loads.
// ---------------------------------------------------------------------------
#define GBM 128
#define GBN 128
#define CHK 16                          // k per chunk (halfs)
#define NST 8
#define A_STG_H (GBM * CHK)             // 2048 halfs
#define B_STG_H (GBN * CHK)             // 2048 halfs
#define STG_HALFS (A_STG_H + B_STG_H)   // 4096
#define STG_BYTES (STG_HALFS * 2)       // 8192
#define GEMM_SMEM (NST * STG_BYTES + 128)

__global__ __launch_bounds__(320, 2)
void gemm_f16_kernel(const __half* __restrict__ A,
                     const __half* __restrict__ B,
                     const float* __restrict__ skip,
                     float* __restrict__ C,
                     int M, int N, int K) {
    extern __shared__ __half smh[];
    uint32_t smbase = (uint32_t)__cvta_generic_to_shared(smh);
    uint32_t mbar   = smbase + NST * STG_BYTES;
    // full[s] = mbar + s*8 ; empty[s] = mbar + 64 + s*8

    int t   = threadIdx.x;
    int m0  = blockIdx.y * GBM;
    int n0  = blockIdx.x * GBN;
    int nk  = K / CHK;   // 64
    int nko = nk / NST;  // 8

    if (t == 0) {
        #pragma unroll
        for (int s = 0; s < NST; s++) {
            MBAR_INIT(mbar + s * 8, 64);        // full: 64 producer threads
            MBAR_INIT(mbar + 64 + s * 8, 8);    // empty: 8 consumer warps
        }
    }
    __syncthreads();

    if (t >= 256) {
        // ----- producer: 64 threads; per chunk 512 cp16 -> 8 each -----
        int p = t - 256;
        const __half* src[8];
        uint32_t dst[8];
        #pragma unroll
        for (int i = 0; i < 8; i++) {
            int id = p + 64 * i;          // 0..511
            int r  = (id >> 1) & 127;     // row within A or B
            int q  = id & 1;              // 8-half group
            bool isB = (id >= 256);
            src[i] = (isB ? B + (size_t)(n0 + r) * K : A + (size_t)(m0 + r) * K) + q * 8;
            dst[i] = smbase + (isB ? A_STG_H * 2 : 0) + (r * CHK + q * 8) * 2;
        }
        int koff = 0;
        for (int ko = 0; ko < nko; ko++) {
            int ph = 1 ^ (ko & 1);
            #pragma unroll
            for (int s = 0; s < NST; s++) {
                MBAR_WAIT_PARITY(mbar + 64 + s * 8, ph);
                const uint32_t soff = s * STG_BYTES;
                const int kofs = koff + s * CHK;
                #pragma unroll
                for (int i = 0; i < 8; i++)
                    cp16(dst[i] + soff, src[i] + kofs);
                CPASYNC_MBAR_ARRIVE(mbar + s * 8);
            }
            koff += NST * CHK;
        }
        return;
    }

    // ----- consumers: 8 warps, 32x64 tiles (4 m-groups x 2 n-groups) -----
    int lane = t & 31;
    int wid  = t >> 5;
    int wm   = (wid >> 1) * 32;
    int wn   = (wid & 1) * 64;
    int gid  = lane >> 2;
    int tig  = lane & 3;

    // per-thread fragment base offsets (halfs) within a stage
    const int aoff = (wm + gid) * CHK + tig * 4;
    const int boff = A_STG_H + (wn + gid) * CHK + tig * 4;

    float acc[2][8][4] = {};

    for (int ko = 0; ko < nko; ko++) {
        int ph = ko & 1;
        #pragma unroll
        for (int s = 0; s < NST; s++) {
            MBAR_WAIT_PARITY(mbar + s * 8, ph);
            const __half* sbase = smh + s * STG_HALFS;
            // A frags: 4 LDS.64  (x = k-lo pair, y = k-hi pair)
            uint2 a00 = *(const uint2*)(sbase + aoff);
            uint2 a01 = *(const uint2*)(sbase + aoff + 8 * CHK);
            uint2 a10 = *(const uint2*)(sbase + aoff + 16 * CHK);
            uint2 a11 = *(const uint2*)(sbase + aoff + 24 * CHK);
            #pragma unroll
            for (int ni = 0; ni < 8; ni++) {
                uint2 bb = *(const uint2*)(sbase + boff + (ni * 8) * CHK);
                mma_f16(acc[0][ni], a00.x, a01.x, a00.y, a01.y, bb.x, bb.y);
                mma_f16(acc[1][ni], a10.x, a11.x, a10.y, a11.y, bb.x, bb.y);
            }
            __syncwarp();
            if (lane == 0) MBAR_ARRIVE(mbar + 64 + s * 8);
        }
    }

    // epilogue (fp32 accumulators)
    #pragma unroll
    for (int mi = 0; mi < 2; mi++) {
        #pragma unroll
        for (int ni = 0; ni < 8; ni++) {
            int r0  = m0 + wm + mi * 16 + gid;
            int col = n0 + wn + ni * 8 + tig * 2;
            float2 v0 = make_float2(acc[mi][ni][0], acc[mi][ni][1]);
            float2 v1 = make_float2(acc[mi][ni][2], acc[mi][ni][3]);
            size_t o0 = (size_t)r0 * N + col;
            size_t o1 = (size_t)(r0 + 8) * N + col;
            if (skip) {
                float2 s0 = *(const float2*)(skip + o0);
                float2 s1 = *(const float2*)(skip + o1);
                v0.x += s0.x; v0.y += s0.y;
                v1.x += s1.x; v1.y += s1.y;
            }
            *(float2*)(C + o0) = v0;
            *(float2*)(C + o1) = v1;
        }
    }
}

// ---------------------------------------------------------------------------
// Banded attention TQ=32 (tf32 mma.sync), Qs/Ss smem aliasing, 2 CTAs/SM.
// Output written fp16 K-PACKED (16-group interleave) into g_attp.
// ---------------------------------------------------------------------------
#define TQ   32
#define SPAN 160
#define QST  68
#define KSTR 68
#define VTST 165
#define SST  165
#define ATTN_SMEM ((TQ * SST + SPAN * KSTR + DHEAD * VTST) * sizeof(float))

__global__ __launch_bounds__(256, 2) void attn_kernel() {
    extern __shared__ float sm[];
    float* Ss = sm;                       // TQ * SST (aliases Qs)
    float* Qs = sm;                       // TQ * QST (dead after frag load)
    float* Ks = sm + TQ * SST;            // SPAN * KSTR
    float* Vt = Ks + SPAN * KSTR;         // DHEAD * VTST

    int t    = threadIdx.x;
    int lane = t & 31;
    int w    = t >> 5;
    int gid  = lane >> 2;
    int tig  = lane & 3;
    int bh = blockIdx.y;
    int b  = bh >> 4, h = bh & 15;
    int q0 = blockIdx.x * TQ;
    int kstart = q0 - HALFW;
    size_t base = (size_t)(b * SEQ) * N3;

    for (int idx = t; idx < TQ * 16; idx += 256) {
        int i  = idx >> 4;
        int d4 = idx & 15;
        float4 v = *(const float4*)&g_qkv[base + (size_t)(q0 + i) * N3 + h * DHEAD + d4 * 4];
        float* dst = &Qs[i * QST + d4 * 4];
        dst[0] = __uint_as_float(f2tf32(v.x));
        dst[1] = __uint_as_float(f2tf32(v.y));
        dst[2] = __uint_as_float(f2tf32(v.z));
        dst[3] = __uint_as_float(f2tf32(v.w));
    }
    for (int idx = t; idx < SPAN * 16; idx += 256) {
        int jj = idx >> 4;
        int d4 = idx & 15;
        int j  = kstart + jj;
        float4 kv = make_float4(0, 0, 0, 0), vv = kv;
        if (j >= 0 && j < SEQ) {
            kv = *(const float4*)&g_qkv[base + (size_t)j * N3 + DIM     + h * DHEAD + d4 * 4];
            vv = *(const float4*)&g_qkv[base + (size_t)j * N3 + 2 * DIM + h * DHEAD + d4 * 4];
        }
        float* kd = &Ks[jj * KSTR + d4 * 4];
        kd[0] = __uint_as_float(f2tf32(kv.x));
        kd[1] = __uint_as_float(f2tf32(kv.y));
        kd[2] = __uint_as_float(f2tf32(kv.z));
        kd[3] = __uint_as_float(f2tf32(kv.w));
        int d0 = d4 * 4;
        Vt[(d0 + 0) * VTST + jj] = __uint_as_float(f2tf32(vv.x));
        Vt[(d0 + 1) * VTST + jj] = __uint_as_float(f2tf32(vv.y));
        Vt[(d0 + 2) * VTST + jj] = __uint_as_float(f2tf32(vv.z));
        Vt[(d0 + 3) * VTST + jj] = __uint_as_float(f2tf32(vv.w));
    }
    __syncthreads();

    // Q fragments to registers, then barrier so Ss may overwrite Qs.
    int mt = w & 1;
    int ng = w >> 1;
    unsigned afr[8][4];
    {
        int mr = mt * 16 + gid;
        #pragma unroll
        for (int kk = 0; kk < 8; kk++) {
            int kb = kk * 8;
            afr[kk][0] = __float_as_uint(Qs[mr * QST + kb + tig]);
            afr[kk][1] = __float_as_uint(Qs[(mr + 8) * QST + kb + tig]);
            afr[kk][2] = __float_as_uint(Qs[mr * QST + kb + tig + 4]);
            afr[kk][3] = __float_as_uint(Qs[(mr + 8) * QST + kb + tig + 4]);
        }
    }
    __syncthreads();

    // S = Q K^T / 8, band-masked
    {
        #pragma unroll
        for (int l = 0; l < 5; l++) {
            int nt = ng * 5 + l;
            int nr = nt * 8 + gid;
            float acc[4] = {0.f, 0.f, 0.f, 0.f};
            #pragma unroll
            for (int kk = 0; kk < 8; kk++) {
                unsigned bfr[2];
                bfr[0] = __float_as_uint(Ks[nr * KSTR + kk * 8 + tig]);
                bfr[1] = __float_as_uint(Ks[nr * KSTR + kk * 8 + tig + 4]);
                mma_tf32(acc, afr[kk], bfr);
            }
            int i0  = mt * 16 + gid;
            int col = nt * 8 + tig * 2;
            #pragma unroll
            for (int rr = 0; rr < 2; rr++) {
                int i = i0 + rr * 8;
                int qi = q0 + i;
                #pragma unroll
                for (int c = 0; c < 2; c++) {
                    int jj = col + c;
                    int j  = kstart + jj;
                    int di = qi - j; if (di < 0) di = -di;
                    bool valid = (j >= 0) && (j < SEQ) && (di <= HALFW);
                    Ss[i * SST + jj] = valid ? acc[rr * 2 + c] * 0.125f : -1e30f;
                }
            }
        }
    }
    __syncthreads();

    // softmax
    #pragma unroll
    for (int r = 0; r < 4; r++) {
        int i = w * 4 + r;
        float vals[5];
        float vmax = -1e30f;
        #pragma unroll
        for (int c = 0; c < 5; c++) {
            vals[c] = Ss[i * SST + lane + 32 * c];
            vmax = fmaxf(vmax, vals[c]);
        }
        #pragma unroll
        for (int off = 16; off > 0; off >>= 1)
            vmax = fmaxf(vmax, __shfl_xor_sync(0xffffffff, vmax, off));
        float sum = 0.0f;
        #pragma unroll
        for (int c = 0; c < 5; c++) {
            vals[c] = __expf(vals[c] - vmax);
            sum += vals[c];
        }
        #pragma unroll
        for (int off = 16; off > 0; off >>= 1)
            sum += __shfl_xor_sync(0xffffffff, sum, off);
        float inv = 1.0f / sum;
        #pragma unroll
        for (int c = 0; c < 5; c++)
            Ss[i * SST + lane + 32 * c] = __uint_as_float(f2tf32(vals[c] * inv));
    }
    __syncthreads();

    // O = P V ; epilogue writes fp16 packed (16-group interleave)
    {
        float acc0[4] = {0.f, 0.f, 0.f, 0.f};
        float acc1[4] = {0.f, 0.f, 0.f, 0.f};
        int n0r = ng * 8 + gid;
        int n1r = (ng + 4) * 8 + gid;
        #pragma unroll
        for (int kk = 0; kk < 20; kk++) {
            int kb = kk * 8;
            int mr = mt * 16 + gid;
            unsigned pfr[4];
            pfr[0] = __float_as_uint(Ss[mr * SST + kb + tig]);
            pfr[1] = __float_as_uint(Ss[(mr + 8) * SST + kb + tig]);
            pfr[2] = __float_as_uint(Ss[mr * SST + kb + tig + 4]);
            pfr[3] = __float_as_uint(Ss[(mr + 8) * SST + kb + tig + 4]);
            unsigned b0[2], b1[2];
            b0[0] = __float_as_uint(Vt[n0r * VTST + kb + tig]);
            b0[1] = __float_as_uint(Vt[n0r * VTST + kb + tig + 4]);
            b1[0] = __float_as_uint(Vt[n1r * VTST + kb + tig]);
            b1[1] = __float_as_uint(Vt[n1r * VTST + kb + tig + 4]);
            mma_tf32(acc0, pfr, b0);
            mma_tf32(acc1, pfr, b1);
        }
        // packed pos for element k within a 16-group:
        // pos(k) = ((k&7)>>1)*4 + (k>>3)*2 + (k&1); pairs (2t,2t+1) adjacent.
        size_t ob = (size_t)(b * SEQ + q0) * DIM + h * DHEAD;
        int r0 = mt * 16 + gid;
        #pragma unroll
        for (int rr = 0; rr < 2; rr++) {
            int row = r0 + rr * 8;
            __half* orow = &g_attp[ob + (size_t)row * DIM];
            #pragma unroll
            for (int pair = 0; pair < 2; pair++) {
                int colg = (pair == 0) ? ng * 8 : (ng + 4) * 8;
                float vx = (pair == 0) ? acc0[rr * 2]     : acc1[rr * 2];
                float vy = (pair == 0) ? acc0[rr * 2 + 1] : acc1[rr * 2 + 1];
                int off16 = (colg & 8) | (tig * 2);
                int pos   = ((off16 & 7) >> 1) * 4 + ((off16 >> 3) * 2);
                *(__half2*)(orow + (colg & ~15) + pos) = __floats2half2_rn(vx, vy);
            }
        }
    }
}

// ---------------------------------------------------------------------------
// launch
// ---------------------------------------------------------------------------
extern "C" void kernel_launch(void* const* d_in, const int* in_sizes, int n_in,
                              void* d_out, int out_size) {
    const float* x      = (const float*)d_in[0];
    const float* w_norm = (const float*)d_in[1];
    const float* w_qkv  = (const float*)d_in[2];
    const float* w_out  = (const float*)d_in[3];
    float* out = (float*)d_out;

    float* p_qkv;
    __half *p_xnp, *p_attp, *p_wqp, *p_wop;
    cudaGetSymbolAddress((void**)&p_qkv,  g_qkv);
    cudaGetSymbolAddress((void**)&p_xnp,  g_xnp);
    cudaGetSymbolAddress((void**)&p_attp, g_attp);
    cudaGetSymbolAddress((void**)&p_wqp,  g_wqkvp);
    cudaGetSymbolAddress((void**)&p_wop,  g_woutp);

    cudaFuncSetAttribute(gemm_f16_kernel, cudaFuncAttributeMaxDynamicSharedMemorySize,
                         (int)GEMM_SMEM);
    cudaFuncSetAttribute(attn_kernel, cudaFuncAttributeMaxDynamicSharedMemorySize,
                         (int)ATTN_SMEM);

    // 0. pack weights -> fp16 K-interleaved
    pack_kernel<<<(N3 * DIM / 16) / 256, 256>>>(w_qkv, p_wqp);
    pack_kernel<<<(DIM * DIM / 16) / 256, 256>>>(w_out, p_wop);

    // 1. RMSNorm -> packed fp16 xn
    rmsnorm_kernel<<<MROWS, 64>>>(x, w_norm);

    // 2. QKV projection (fp16 tensor cores, warp-specialized, 2 CTA/SM)
    {
        dim3 grid(N3 / GBN, MROWS / GBM);
        gemm_f16_kernel<<<grid, 320, GEMM_SMEM>>>(p_xnp, p_wqp, nullptr, p_qkv,
                                                  MROWS, N3, DIM);
    }

    // 3. Banded attention (TQ=32, 2 CTA/SM) -> packed fp16 att
    {
        dim3 grid(SEQ / TQ, BATCH * HEADS);
        attn_kernel<<<grid, 256, ATTN_SMEM>>>();
    }

    // 4. Output projection + residual (fp16 tensor cores)
    {
        dim3 grid(DIM / GBN, MROWS / GBM);
        gemm_f16_kernel<<<grid, 320, GEMM_SMEM>>>(p_attp, p_wop, x, out,
                                                  MROWS, DIM, DIM);
    }
}